// round 1
// baseline (speedup 1.0000x reference)
#include <cuda_runtime.h>
#include <cstdint>

// TotalDegree: out[b, t] = prod_d x[b, d]^E[t, d], for all multisets of size 0..4
// over 8 variables, in lexicographic (preorder-DFS) order. nterms = 495.
//
// Strategy: compile-time table of byte-packed index quadruples (index 8 == "1.0"),
// warp-per-row, lane-strided terms -> fully coalesced stores. HBM-write bound.

#define NTERMS 495
#define DIM 8

struct Tbl { unsigned v[NTERMS]; };

constexpr unsigned pack4(int a, int b, int c, int d) {
    return (unsigned)a | ((unsigned)b << 8) | ((unsigned)c << 16) | ((unsigned)d << 24);
}

// Preorder DFS over non-decreasing tuples == sorted lexicographic order of the
// reference's chained combinations_with_replacement (prefix sorts before extension).
constexpr Tbl make_tbl() {
    Tbl t{};
    int n = 0;
    t.v[n++] = pack4(8, 8, 8, 8);                       // degree 0: constant 1
    for (int a = 0; a < DIM; a++) {
        t.v[n++] = pack4(a, 8, 8, 8);                   // degree 1
        for (int b = a; b < DIM; b++) {
            t.v[n++] = pack4(a, b, 8, 8);               // degree 2
            for (int c = b; c < DIM; c++) {
                t.v[n++] = pack4(a, b, c, 8);           // degree 3
                for (int d = c; d < DIM; d++) {
                    t.v[n++] = pack4(a, b, c, d);       // degree 4
                }
            }
        }
    }
    return t;
}

// Static-initialized device global: embedded in the cubin, no runtime copy needed.
__device__ const Tbl g_tbl = make_tbl();

__global__ void __launch_bounds__(256)
totaldegree_kernel(const float* __restrict__ x, float* __restrict__ out, int nrows) {
    __shared__ float s_x[8][12];   // 8 warps per block; 9 live words, padded stride
    const int warp = threadIdx.x >> 5;
    const int lane = threadIdx.x & 31;
    const int row  = (blockIdx.x << 3) + warp;
    if (row >= nrows) return;

    if (lane < DIM) s_x[warp][lane] = x[(size_t)row * DIM + lane];
    if (lane == DIM) s_x[warp][DIM] = 1.0f;   // identity slot for padded indices
    __syncwarp();

    const float* rx = s_x[warp];
    float* o = out + (size_t)row * NTERMS;

    #pragma unroll
    for (int t = lane; t < NTERMS; t += 32) {
        const unsigned p = g_tbl.v[t];           // stride-1 per warp, L1-resident
        const float v = rx[p & 255u]
                      * rx[(p >> 8) & 255u]
                      * rx[(p >> 16) & 255u]
                      * rx[p >> 24];
        o[t] = v;                                // stride-1 per warp -> coalesced
    }
}

extern "C" void kernel_launch(void* const* d_in, const int* in_sizes, int n_in,
                              void* d_out, int out_size) {
    const float* x = (const float*)d_in[0];
    float* out = (float*)d_out;
    const int nrows = in_sizes[0] / DIM;
    const int blocks = (nrows + 7) / 8;          // 8 warps (rows) per block
    totaldegree_kernel<<<blocks, 256>>>(x, out, nrows);
}

// round 2
// speedup vs baseline: 1.1606x; 1.1606x over previous
#include <cuda_runtime.h>
#include <cstdint>

// TotalDegree: out[b, t] = prod over sorted index multisets (deg 0..4) of x[b,.].
// nterms = 495, dim = 8, lexicographic (preorder-DFS) order.
//
// R2 strategy: every deg<=4 monomial = product of two deg<=2 "pair values".
// 45 pair values per row (1, x_a, x_a*x_b), built once per row via warp shuffles,
// held in shared. Each term: 1 ushort table load + 2 LDS + 1 FMUL + 1 coalesced STG.

#define NTERMS 495
#define NVALS  45    // pairs (a,b), 0 <= a <= b <= 8, where index 8 == "1.0"
#define DIM    8

// Upper-triangular pair id: 0 <= a <= b <= 8  ->  [0, 45)
constexpr int vid(int a, int b) {
    return a * 9 - a * (a - 1) / 2 + (b - a);
}

struct T16 { unsigned short v[NTERMS]; };
struct Dec { unsigned char v[NVALS]; };

// Term table: DFS over non-decreasing tuples (== reference lexicographic order).
// Each term's sorted indices (i0<=i1<=i2<=i3, padded with 8) split into
// pair(i0,i1) * pair(i2,i3); store the two pair-ids as bytes.
constexpr T16 make_tbl() {
    T16 t{};
    int n = 0;
    const int one = vid(8, 8);                                   // id 44 -> 1.0
    t.v[n++] = (unsigned short)(one | (one << 8));               // degree 0
    for (int a = 0; a < DIM; a++) {
        t.v[n++] = (unsigned short)(vid(a, 8) | (one << 8));     // degree 1
        for (int b = a; b < DIM; b++) {
            t.v[n++] = (unsigned short)(vid(a, b) | (one << 8)); // degree 2
            for (int c = b; c < DIM; c++) {
                t.v[n++] = (unsigned short)(vid(a, b) | (vid(c, 8) << 8)); // deg 3
                for (int d = c; d < DIM; d++) {
                    t.v[n++] = (unsigned short)(vid(a, b) | (vid(c, d) << 8)); // deg 4
                }
            }
        }
    }
    return t;
}

// Decode table for building the 45 pair values: id -> (a | b<<4)
constexpr Dec make_dec() {
    Dec d{};
    for (int a = 0; a <= 8; a++)
        for (int b = a; b <= 8; b++)
            d.v[vid(a, b)] = (unsigned char)(a | (b << 4));
    return d;
}

__device__ const T16 g_tbl = make_tbl();
__device__ const Dec g_dec = make_dec();

__global__ void __launch_bounds__(256)
totaldegree_kernel(const float* __restrict__ x, float* __restrict__ out, int nrows) {
    __shared__ float s_v[8][NVALS + 3];   // 8 warps/block; 45 pair-values per row
    const int warp = threadIdx.x >> 5;
    const int lane = threadIdx.x & 31;
    const int row  = (blockIdx.x << 3) + warp;
    if (row >= nrows) return;             // warp-uniform guard

    // Lane l < 8 holds x[row, l]; all other lanes hold 1.0 (the "index 8" slot).
    float xv = 1.0f;
    if (lane < DIM) xv = x[(size_t)row * DIM + lane];

    // Build the 45 pair values: v[id] = x[a] * x[b] via warp shuffles.
    {
        const unsigned d0 = g_dec.v[lane];                      // ids 0..31
        const float a0 = __shfl_sync(0xffffffffu, xv, d0 & 15u);
        const float b0 = __shfl_sync(0xffffffffu, xv, d0 >> 4);
        s_v[warp][lane] = a0 * b0;

        const int k = lane + 32;                                // ids 32..44
        const unsigned d1 = g_dec.v[k < NVALS ? k : NVALS - 1];
        const float a1 = __shfl_sync(0xffffffffu, xv, d1 & 15u);
        const float b1 = __shfl_sync(0xffffffffu, xv, d1 >> 4);
        if (k < NVALS) s_v[warp][k] = a1 * b1;
    }
    __syncwarp();

    const float* V = s_v[warp];
    float* o = out + (size_t)row * NTERMS;

    #pragma unroll
    for (int i = 0; i < 16; i++) {
        const int t = lane + i * 32;
        if (t < NTERMS) {                                       // only trims last iter
            const unsigned p = g_tbl.v[t];                      // 64B/warp, L1-resident
            o[t] = V[p & 255u] * V[p >> 8];                     // coalesced store
        }
    }
}

extern "C" void kernel_launch(void* const* d_in, const int* in_sizes, int n_in,
                              void* d_out, int out_size) {
    const float* x = (const float*)d_in[0];
    float* out = (float*)d_out;
    const int nrows = in_sizes[0] / DIM;
    const int blocks = (nrows + 7) / 8;       // 8 warps (rows) per block
    totaldegree_kernel<<<blocks, 256>>>(x, out, nrows);
}